// round 13
// baseline (speedup 1.0000x reference)
#include <cuda_runtime.h>
#include <cuda_fp16.h>
#include <cstdint>

#define DI __device__ __forceinline__

// ---------------- problem sizes ----------------
#define MV    32000   // vocab
#define NH    2048    // hidden
#define DIMV  1024    // embed dim
#define BATCH 2048    // batch
#define KG    (NH + DIMV)   // 3072 (gate GEMM K)
#define KA    NH            // 2048 (W_A GEMM K)

// ---------------- device scratch (allocation-free rule) ----------------
// g_Wg rows are INTERLEAVED: tile t (256 rows) = [f rows 64t..64t+64) | i | o | c~]
__device__ __align__(128) __half g_Wg[(size_t)4 * NH * KG];
__device__ __align__(128) __half g_WA[(size_t)MV * KA];           // fp16 W_A
__device__ __align__(128) __half g_zT[(size_t)BATCH * KG];        // z^T  [B][3072] K-major
__device__ __align__(128) __half g_hT[(size_t)BATCH * KA];        // h^T  [B][2048] K-major

// ---------------- PTX helpers (sm_80-era: valid on plain sm_103 target) ----------------
DI uint32_t smem_u32(const void* p) {
    uint32_t a;
    asm("{ .reg .u64 t; cvta.to.shared.u64 t, %1; cvt.u32.u64 %0, t; }" : "=r"(a) : "l"(p));
    return a;
}

DI void ldsm_x4(uint32_t* r, uint32_t addr) {
    asm volatile("ldmatrix.sync.aligned.m8n8.x4.shared.b16 {%0,%1,%2,%3}, [%4];"
                 : "=r"(r[0]), "=r"(r[1]), "=r"(r[2]), "=r"(r[3]) : "r"(addr));
}

DI void mma16816(float* c, const uint32_t* a, uint32_t b0, uint32_t b1) {
    asm volatile("mma.sync.aligned.m16n8k16.row.col.f32.f16.f16.f32 "
                 "{%0,%1,%2,%3}, {%4,%5,%6,%7}, {%8,%9}, {%0,%1,%2,%3};"
                 : "+f"(c[0]), "+f"(c[1]), "+f"(c[2]), "+f"(c[3])
                 : "r"(a[0]), "r"(a[1]), "r"(a[2]), "r"(a[3]), "r"(b0), "r"(b1));
}

#define CP_ASYNC16(dst, src) \
    asm volatile("cp.async.cg.shared.global [%0], [%1], 16;" :: "r"(dst), "l"(src) : "memory")
#define CP_COMMIT() asm volatile("cp.async.commit_group;" ::: "memory")
#define CP_WAIT(n)  asm volatile("cp.async.wait_group %0;" :: "n"(n) : "memory")

// ---------------- GEMM: D[m][n] = sum_k A[m][k]*B[n][k], A,B fp16 K-major ----------------
// BM=256, BN=128, BK=64 (128B rows, XOR-16B swizzle). 4-stage cp.async pipeline,
// 192KB smem -> 1 CTA/SM (16 warps/SM). 512 threads = 16 warps as 4(m) x 4(n):
// warp tile 64x32 (the proven reg-fit). 4 stages + load-ahead 2 makes
// __syncthreads every SECOND chunk provably race-free (stage written at iter c was
// last read at chunk c-2; the even-iter sync guarantees all warps >= c-1).
#define NSTAGE 4
#define STAGE_BYTES 49152            // A tile 32KB + B tile 16KB
#define GEMM_SMEM (NSTAGE * STAGE_BYTES)  // 196608

// 6 cp.async per thread (512 threads): A rows (tid>>3)+64j (j<4), B rows +64j (j<2)
template <int KK>
DI void issue_loads(const __half* a, const __half* b, uint32_t dstA, uint32_t dstB) {
#pragma unroll
    for (int it = 0; it < 4; ++it)
        CP_ASYNC16(dstA + (uint32_t)(it * 8192), a + (size_t)it * 64 * KK);
#pragma unroll
    for (int it = 0; it < 2; ++it)
        CP_ASYNC16(dstB + (uint32_t)(it * 8192), b + (size_t)it * 64 * KK);
}

DI float sigmoidf_(float v) { return 1.0f / (1.0f + __expf(-v)); }

#define GEMM0_CTAS 512    // (8192/256) * (2048/128)
#define CONV_CTAS  512    // trailing CTAs of gemm0 grid: convert W_A under the GEMM

// MODE 0: gates GEMM over interleaved g_Wg + fused LSTM-cell epilogue
//         + trailing CTAs convert W_A f32 -> g_WA fp16 (DRAM idle under GEMM)
// MODE 1: W_A GEMM  (A=g_WA [32000][2048], B=g_hT, bias epilogue -> y)
template <int MODE>
__global__ void __launch_bounds__(512, 1)
gemm_f16(const float* __restrict__ bias0, const float* __restrict__ bias1,
         const float* __restrict__ bias2, const float* __restrict__ bias3,
         float* __restrict__ outy, const float4* __restrict__ convsrc,
         const float* __restrict__ Cprev, float* __restrict__ outC) {
    constexpr int KK  = (MODE == 0) ? KG : KA;
    constexpr int NCH = KK / 64;

    if (MODE == 0 && blockIdx.x >= GEMM0_CTAS) {
        // ---- fused W_A conversion (grid-stride) ----
        const size_t N4 = (size_t)MV * KA / 4;
        size_t i = (size_t)(blockIdx.x - GEMM0_CTAS) * 512 + threadIdx.x;
        const size_t stride = (size_t)CONV_CTAS * 512;
        for (; i < N4; i += stride) {
            float4 v = convsrc[i];
            __half2* d = (__half2*)(g_WA + i * 4);
            d[0] = __floats2half2_rn(v.x, v.y);
            d[1] = __floats2half2_rn(v.z, v.w);
        }
        return;
    }

    const __half* A = (MODE == 0) ? g_Wg : g_WA;
    const __half* B = (MODE == 0) ? g_zT : g_hT;

    extern __shared__ __align__(1024) char smem[];
    const uint32_t sbase = smem_u32(smem);
    const int tid = threadIdx.x;
    const int lane = tid & 31;
    const int warp = tid >> 5;
    const int warpm = warp & 3;       // 4 warps over m: warp tile 64 rows
    const int warpn = warp >> 2;      // 4 warps over n: warp tile 32 cols

    // n fastest -> 16 consecutive CTAs share one A tile (L2 reuse of big operand)
    const int n0 = (blockIdx.x & 15) * 128;
    const int m0 = (blockIdx.x >> 4) * 256;

    float acc[4][4][4];
#pragma unroll
    for (int i = 0; i < 4; ++i)
#pragma unroll
        for (int j = 0; j < 4; ++j)
#pragma unroll
            for (int k = 0; k < 4; ++k) acc[i][j][k] = 0.0f;

    const int lrow = lane & 15;
    const int lhi  = lane >> 4;

    // hoisted ldsm offsets (relative to stage base); per-kstep addr = base ^ (kk<<5)
    uint32_t aoff[4], boff[2];
#pragma unroll
    for (int mt = 0; mt < 4; ++mt) {
        const int row = warpm * 64 + mt * 16 + lrow;
        aoff[mt] = (uint32_t)row * 128u + (uint32_t)((lhi ^ (row & 7)) << 4);
    }
#pragma unroll
    for (int np = 0; np < 2; ++np) {
        const int nrow = warpn * 32 + np * 16 + lrow;
        boff[np] = 32768u + (uint32_t)nrow * 128u + (uint32_t)((lhi ^ (nrow & 7)) << 4);
    }

    // loader per-thread state (strength-reduced): base pointers + fixed smem offsets
    const int ltr = tid >> 3;         // base row 0..63
    const int ltc = tid & 7;          // 16B-group column
    const uint32_t dA = (uint32_t)ltr * 128u + (uint32_t)((ltc ^ (ltr & 7)) << 4);
    const uint32_t dB = 32768u + dA;  // same formula for the B half of the stage
    const __half* aL = A + (size_t)(m0 + ltr) * KK + ltc * 8;
    const __half* bL = B + (size_t)(n0 + ltr) * KK + ltc * 8;

    // prologue: 2 chunks in flight (load-ahead 2)
    issue_loads<KK>(aL, bL, sbase + dA, sbase + dB);
    CP_COMMIT();
    issue_loads<KK>(aL + 64, bL + 64, sbase + STAGE_BYTES + dA, sbase + STAGE_BYTES + dB);
    CP_COMMIT();
    aL += 128; bL += 128;

    int ldst = 2;   // stage receiving the next load
    int cst  = 0;   // stage being computed
    for (int c = 0; c < NCH; ++c) {
        CP_WAIT(1);                       // chunk c complete
        if ((c & 1) == 0) __syncthreads(); // every 2nd chunk is enough with 4 stages

        if (c + 2 < NCH) {   // prefetch chunk c+2 into stage last read at chunk c-2
            issue_loads<KK>(aL, bL, sbase + (uint32_t)ldst * STAGE_BYTES + dA,
                            sbase + (uint32_t)ldst * STAGE_BYTES + dB);
            aL += 64; bL += 64;
            ldst = (ldst + 1 == NSTAGE) ? 0 : ldst + 1;
        }
        CP_COMMIT();

        const uint32_t sa = sbase + (uint32_t)cst * STAGE_BYTES;
        cst = (cst + 1 == NSTAGE) ? 0 : cst + 1;
#pragma unroll
        for (int kk = 0; kk < 4; ++kk) {
            const uint32_t kx = (uint32_t)(kk << 5);
            uint32_t afr[4][4];
#pragma unroll
            for (int mt = 0; mt < 4; ++mt)
                ldsm_x4(afr[mt], sa + (aoff[mt] ^ kx));
            uint32_t bfr[2][4];
#pragma unroll
            for (int np = 0; np < 2; ++np)
                ldsm_x4(bfr[np], sa + (boff[np] ^ kx));
#pragma unroll
            for (int mt = 0; mt < 4; ++mt)
#pragma unroll
                for (int nt = 0; nt < 4; ++nt)
                    mma16816(acc[mt][nt], afr[mt], bfr[nt >> 1][nt & 1], bfr[nt >> 1][(nt & 1) + 2]);
        }
    }

    const int qr = lane >> 2;          // 0..7
    const int qc = (lane & 3) * 2;     // 0,2,4,6

    if (MODE == 1) {
        // ---------------- gemm1 epilogue: bias + direct float2 stores ----------------
#pragma unroll
        for (int mt = 0; mt < 4; ++mt) {
            const int r1 = m0 + warpm * 64 + mt * 16 + qr;
            const float bv0 = bias0[r1];
            const float bv1 = bias0[r1 + 8];
#pragma unroll
            for (int nt = 0; nt < 4; ++nt) {
                const int col = n0 + warpn * 32 + nt * 8 + qc;
                float2 v0, v1;
                v0.x = acc[mt][nt][0] + bv0;
                v0.y = acc[mt][nt][1] + bv0;
                v1.x = acc[mt][nt][2] + bv1;
                v1.y = acc[mt][nt][3] + bv1;
                *(float2*)(outy + (size_t)r1 * BATCH + col) = v0;
                *(float2*)(outy + (size_t)(r1 + 8) * BATCH + col) = v1;
            }
        }
        return;
    }

    // ---------------- gemm0 fused LSTM-cell epilogue ----------------
    // local rows [0..64)=f, [64..128)=i, [128..192)=o, [192..256)=c~ ; hidden g0..g0+64
    const int g0 = (m0 >> 8) * 64;
    float* sbuf = (float*)smem;                 // [256][132] raw gate accs (135KB)
    float* hbuf = sbuf + 256 * 132;             // [64][132] h values (34KB)
    __syncthreads();                            // mainloop smem reads done before reuse

    // Phase 1: accs -> smem
#pragma unroll
    for (int mt = 0; mt < 4; ++mt) {
        const int r1 = warpm * 64 + mt * 16 + qr;
#pragma unroll
        for (int nt = 0; nt < 4; ++nt) {
            const int col = warpn * 32 + nt * 8 + qc;
            sbuf[r1 * 132 + col]           = acc[mt][nt][0];
            sbuf[r1 * 132 + col + 1]       = acc[mt][nt][1];
            sbuf[(r1 + 8) * 132 + col]     = acc[mt][nt][2];
            sbuf[(r1 + 8) * 132 + col + 1] = acc[mt][nt][3];
        }
    }
    __syncthreads();

    // Phase 2: combine gates per (hidden k, batch b); write C, h; stash h for transpose
    {
        const int k = tid >> 3;                 // 0..63
        const int b0t = (tid & 7) * 16;         // 16 consecutive batch cols
        const int gk = g0 + k;
        const float bf = bias0[gk], bi_ = bias1[gk], bo = bias2[gk], bc = bias3[gk];
        const float* f_r = sbuf + k * 132 + b0t;
        const float* i_r = sbuf + (64 + k) * 132 + b0t;
        const float* o_r = sbuf + (128 + k) * 132 + b0t;
        const float* c_r = sbuf + (192 + k) * 132 + b0t;
        const size_t gofs = (size_t)gk * BATCH + n0 + b0t;
#pragma unroll
        for (int u = 0; u < 16; ++u) {
            const float fs = sigmoidf_(f_r[u] + bf);
            const float is = sigmoidf_(i_r[u] + bi_);
            const float os = sigmoidf_(o_r[u] + bo);
            const float ct = tanhf(c_r[u] + bc);
            const float cc = fs * Cprev[gofs + u] + is * ct;
            const float hh = os * tanhf(cc);
            outC[gofs + u] = cc;
            outy[gofs + u] = hh;                // outy == outH for MODE 0
            hbuf[k * 132 + b0t + u] = hh;
        }
    }
    __syncthreads();

    // Phase 3: h -> g_hT (fp16, K-major) via smem transpose; 32B per thread, coalesced
    {
        const int b = tid >> 2;                 // 0..127
        const int kh = (tid & 3) * 16;          // quarter-row of 16 k's
        uint32_t packed[8];
#pragma unroll
        for (int u = 0; u < 8; ++u) {
            __half2 h2 = __floats2half2_rn(hbuf[(kh + 2 * u) * 132 + b],
                                           hbuf[(kh + 2 * u + 1) * 132 + b]);
            packed[u] = *(uint32_t*)&h2;
        }
        uint4* dst = (uint4*)(g_hT + (size_t)(n0 + b) * KA + g0 + kh);
        dst[0] = make_uint4(packed[0], packed[1], packed[2], packed[3]);
        dst[1] = make_uint4(packed[4], packed[5], packed[6], packed[7]);
    }
}

// ---------------- fused prep: convert_Wg (interleaved) + transpose_h + emb_gather ----------
#define PREP_CONV_CTAS 8192   // one dst row each
#define PREP_TR_CTAS   4096   // (2048/32) x (2048/32)
#define PREP_EMB_CTAS  2048

__global__ void __launch_bounds__(256)
prep_fused(const float4* __restrict__ wf, const float4* __restrict__ wi,
           const float4* __restrict__ wo, const float4* __restrict__ wc,
           const float* __restrict__ h_prev,
           const int* __restrict__ idx, const float* __restrict__ emb) {
    __shared__ float tile[32][33];
    const int bid = blockIdx.x;
    const int tid = threadIdx.x;

    if (bid < PREP_CONV_CTAS) {
        // gate-weight conversion, interleaved row layout for 256-row tiles:
        // dst row m: tile t=m>>8, w=m&255, gate=w>>6, src row = 64t + (w&63)
        const int t = bid >> 8;
        const int w = bid & 255;
        const int gate = w >> 6;
        const int srcrow = t * 64 + (w & 63);
        const float4* s = ((gate == 0) ? wf : (gate == 1) ? wi : (gate == 2) ? wo : wc)
                          + (size_t)srcrow * (KG / 4);
        __half2* d = (__half2*)(g_Wg + (size_t)bid * KG);
#pragma unroll
        for (int i = tid; i < KG / 4; i += 256) {
            float4 v = s[i];
            d[2 * i + 0] = __floats2half2_rn(v.x, v.y);
            d[2 * i + 1] = __floats2half2_rn(v.z, v.w);
        }
    } else if (bid < PREP_CONV_CTAS + PREP_TR_CTAS) {
        // transpose h_prev [2048(n)][2048(b)] -> g_zT[b][n] fp16
        const int b2 = bid - PREP_CONV_CTAS;
        const int b0 = (b2 & 63) * 32;
        const int n0 = (b2 >> 6) * 32;
        const int tx = tid & 31, ty = tid >> 5;   // 32 x 8
#pragma unroll
        for (int j = 0; j < 4; ++j)
            tile[ty + 8 * j][tx] = h_prev[(size_t)(n0 + ty + 8 * j) * BATCH + b0 + tx];
        __syncthreads();
#pragma unroll
        for (int j = 0; j < 4; ++j)
            g_zT[(size_t)(b0 + ty + 8 * j) * KG + n0 + tx] = __float2half(tile[tx][ty + 8 * j]);
    } else {
        const int b = bid - PREP_CONV_CTAS - PREP_TR_CTAS;
        const int r = idx[b];
        const float4* s = (const float4*)(emb + (size_t)r * DIMV);
        __half2* d = (__half2*)(g_zT + (size_t)b * KG + NH);
        float4 v = s[tid];                      // 256 threads, 256 float4
        d[tid * 2 + 0] = __floats2half2_rn(v.x, v.y);
        d[tid * 2 + 1] = __floats2half2_rn(v.z, v.w);
    }
}

// ---------------- launch ----------------
extern "C" void kernel_launch(void* const* d_in, const int* in_sizes, int n_in,
                              void* d_out, int out_size) {
    const int*   itext  = (const int*)d_in[0];
    const float* h_prev = (const float*)d_in[1];
    const float* C_prev = (const float*)d_in[2];
    const float* emb    = (const float*)d_in[3];
    const float* W_A    = (const float*)d_in[4];
    const float* W_C    = (const float*)d_in[5];
    const float* W_f    = (const float*)d_in[6];
    const float* W_o    = (const float*)d_in[7];
    const float* W_i    = (const float*)d_in[8];
    const float* b_A    = (const float*)d_in[9];
    const float* b_C    = (const float*)d_in[10];
    const float* b_f    = (const float*)d_in[11];
    const float* b_o    = (const float*)d_in[12];
    const float* b_i    = (const float*)d_in[13];

    float* outY = (float*)d_out;                       // [32000][2048]
    float* outH = outY + (size_t)MV * BATCH;           // [2048][2048]
    float* outC = outH + (size_t)NH * BATCH;           // [2048][2048]

    cudaFuncSetAttribute(gemm_f16<0>, cudaFuncAttributeMaxDynamicSharedMemorySize, GEMM_SMEM);
    cudaFuncSetAttribute(gemm_f16<1>, cudaFuncAttributeMaxDynamicSharedMemorySize, GEMM_SMEM);

    // fused prep (all inputs of gemm0 in one launch; parts overlap each other)
    prep_fused<<<PREP_CONV_CTAS + PREP_TR_CTAS + PREP_EMB_CTAS, 256>>>(
        (const float4*)W_f, (const float4*)W_i, (const float4*)W_o, (const float4*)W_C,
        h_prev, itext, emb);

    // gate GEMMs (interleaved M=8192, N=2048) + fused cell update + fused W_A conversion
    gemm_f16<0><<<GEMM0_CTAS + CONV_CTAS, 512, GEMM_SMEM>>>(b_f, b_i, b_o, b_C, outH,
                                                            (const float4*)W_A, C_prev, outC);

    // vocab projection
    gemm_f16<1><<<(MV / 256) * (BATCH / 128), 512, GEMM_SMEM>>>(b_A, nullptr, nullptr, nullptr,
                                                                outY, nullptr, nullptr, nullptr);

    (void)in_sizes; (void)n_in; (void)out_size;
}

// round 14
// speedup vs baseline: 1.0676x; 1.0676x over previous
#include <cuda_runtime.h>
#include <cuda_fp16.h>
#include <cstdint>

#define DI __device__ __forceinline__

// ---------------- problem sizes ----------------
#define MV    32000   // vocab
#define NH    2048    // hidden
#define DIMV  1024    // embed dim
#define BATCH 2048    // batch
#define KG    (NH + DIMV)   // 3072 (gate GEMM K)
#define KA    NH            // 2048 (W_A GEMM K)

// ---------------- device scratch (allocation-free rule) ----------------
__device__ __align__(128) __half g_Wg[(size_t)4 * NH * KG];       // fp16 gate weights, stacked f,i,o,C
__device__ __align__(128) __half g_WA[(size_t)MV * KA];           // fp16 W_A
__device__ __align__(128) __half g_zT[(size_t)BATCH * KG];        // z^T  [B][3072] K-major
__device__ __align__(128) __half g_hT[(size_t)BATCH * KA];        // h^T  [B][2048] K-major
__device__ __align__(128) float  g_gates[(size_t)4 * NH * BATCH]; // activated f,i,o,tanh(WCz+b)

// ---------------- PTX helpers (sm_80-era: valid on plain sm_103 target) ----------------
DI uint32_t smem_u32(const void* p) {
    uint32_t a;
    asm("{ .reg .u64 t; cvta.to.shared.u64 t, %1; cvt.u32.u64 %0, t; }" : "=r"(a) : "l"(p));
    return a;
}

DI void ldsm_x4(uint32_t* r, uint32_t addr) {
    asm volatile("ldmatrix.sync.aligned.m8n8.x4.shared.b16 {%0,%1,%2,%3}, [%4];"
                 : "=r"(r[0]), "=r"(r[1]), "=r"(r[2]), "=r"(r[3]) : "r"(addr));
}

DI void mma16816(float* c, const uint32_t* a, uint32_t b0, uint32_t b1) {
    asm volatile("mma.sync.aligned.m16n8k16.row.col.f32.f16.f16.f32 "
                 "{%0,%1,%2,%3}, {%4,%5,%6,%7}, {%8,%9}, {%0,%1,%2,%3};"
                 : "+f"(c[0]), "+f"(c[1]), "+f"(c[2]), "+f"(c[3])
                 : "r"(a[0]), "r"(a[1]), "r"(a[2]), "r"(a[3]), "r"(b0), "r"(b1));
}

#define CP_ASYNC16(dst, src) \
    asm volatile("cp.async.cg.shared.global [%0], [%1], 16;" :: "r"(dst), "l"(src) : "memory")
#define CP_COMMIT() asm volatile("cp.async.commit_group;" ::: "memory")
#define CP_WAIT(n)  asm volatile("cp.async.wait_group %0;" :: "n"(n) : "memory")

// ---------------- GEMM: D[m][n] = sum_k A[m][k]*B[n][k], A,B fp16 K-major ----------------
// BM=BN=128, BK=64 (128B rows, XOR-16B swizzle). 3-stage cp.async pipeline, 96KB smem
// -> 2 CTAs/SM (16 warps/SM). 256 threads = 8 warps as 2(m) x 4(n): warp tile 64x32.
#define NSTAGE 3
#define STAGE_BYTES 32768            // A tile 16KB + B tile 16KB
#define GEMM_SMEM (NSTAGE * STAGE_BYTES)  // 98304

// 8 cp.async per thread (256 threads): A tile rows (tid>>3)+32j, B same
template <int KK>
DI void issue_loads(const __half* a, const __half* b, uint32_t dstA, uint32_t dstB) {
#pragma unroll
    for (int it = 0; it < 4; ++it)
        CP_ASYNC16(dstA + (uint32_t)(it * 4096), a + (size_t)it * 32 * KK);
#pragma unroll
    for (int it = 0; it < 4; ++it)
        CP_ASYNC16(dstB + (uint32_t)(it * 4096), b + (size_t)it * 32 * KK);
}

DI float apply_act(float v, int act) {  // 0: sigmoid, 1: tanh, 2: none
    if (act == 0) return 1.0f / (1.0f + __expf(-v));
    if (act == 1) return tanhf(v);
    return v;
}

#define GEMM0_CTAS 1024   // (8192/128) * (2048/128)
#define CONV_CTAS  1024   // trailing CTAs of gemm0 grid: convert W_A under the GEMM

// MODE 0: gates GEMM (A=g_Wg stacked [8192][3072], B=g_zT, sigmoid/tanh epilogue -> g_gates)
//         + trailing CTAs convert W_A f32 -> g_WA fp16 (DRAM idle under GEMM)
// MODE 1: W_A GEMM  (A=g_WA [32000][2048], B=g_hT, bias epilogue -> y)
template <int MODE>
__global__ void __launch_bounds__(256, 2)
gemm_f16(const float* __restrict__ bias0, const float* __restrict__ bias1,
         const float* __restrict__ bias2, const float* __restrict__ bias3,
         float* __restrict__ outy, const float4* __restrict__ convsrc) {
    constexpr int KK  = (MODE == 0) ? KG : KA;
    constexpr int NCH = KK / 64;

    if (MODE == 0 && blockIdx.x >= GEMM0_CTAS) {
        // ---- fused W_A conversion (grid-stride) ----
        const size_t N4 = (size_t)MV * KA / 4;
        size_t i = (size_t)(blockIdx.x - GEMM0_CTAS) * 256 + threadIdx.x;
        const size_t stride = (size_t)CONV_CTAS * 256;
        for (; i < N4; i += stride) {
            float4 v = convsrc[i];
            __half2* d = (__half2*)(g_WA + i * 4);
            d[0] = __floats2half2_rn(v.x, v.y);
            d[1] = __floats2half2_rn(v.z, v.w);
        }
        return;
    }

    const __half* A = (MODE == 0) ? g_Wg : g_WA;
    const __half* B = (MODE == 0) ? g_zT : g_hT;
    float* outp = (MODE == 0) ? g_gates : outy;

    extern __shared__ __align__(1024) char smem[];
    const uint32_t sbase = smem_u32(smem);
    const int tid = threadIdx.x;
    const int lane = tid & 31;
    const int warp = tid >> 5;
    const int warpm = warp & 1;       // 2 warps over m: warp tile 64
    const int warpn = warp >> 1;      // 4 warps over n: warp tile 32

    // n fastest -> 16 consecutive CTAs share one A tile (L2 reuse of big operand)
    const int n0 = (blockIdx.x & 15) * 128;
    const int m0 = (blockIdx.x >> 4) * 128;

    float acc[4][4][4];
#pragma unroll
    for (int i = 0; i < 4; ++i)
#pragma unroll
        for (int j = 0; j < 4; ++j)
#pragma unroll
            for (int k = 0; k < 4; ++k) acc[i][j][k] = 0.0f;

    const int lrow = lane & 15;
    const int lhi  = lane >> 4;

    // hoisted ldsm offsets (relative to stage base); per-kstep addr = base ^ (kk<<5)
    uint32_t aoff[4], boff[2];
#pragma unroll
    for (int mt = 0; mt < 4; ++mt) {
        const int row = warpm * 64 + mt * 16 + lrow;
        aoff[mt] = (uint32_t)row * 128u + (uint32_t)((lhi ^ (row & 7)) << 4);
    }
#pragma unroll
    for (int np = 0; np < 2; ++np) {
        const int nrow = warpn * 32 + np * 16 + lrow;
        boff[np] = 16384u + (uint32_t)nrow * 128u + (uint32_t)((lhi ^ (nrow & 7)) << 4);
    }

    // loader per-thread state (strength-reduced): base pointers + fixed smem offsets
    const int ltr = tid >> 3;         // base row 0..31
    const int ltc = tid & 7;          // 16B-group column
    const uint32_t dA = (uint32_t)ltr * 128u + (uint32_t)((ltc ^ (ltr & 7)) << 4);
    const uint32_t dB = 16384u + dA;  // same formula for the B half of the stage
    const __half* aptr = A + (size_t)(m0 + ltr) * KK + ltc * 8;
    const __half* bptr = B + (size_t)(n0 + ltr) * KK + ltc * 8;

    // prologue: 2 chunks in flight
    issue_loads<KK>(aptr, bptr, sbase + dA, sbase + dB);
    CP_COMMIT();
    issue_loads<KK>(aptr + 64, bptr + 64, sbase + STAGE_BYTES + dA, sbase + STAGE_BYTES + dB);
    CP_COMMIT();
    aptr += 128; bptr += 128;

    int ldst = 2;   // stage receiving the next load
    int cst  = 0;   // stage being computed
    for (int c = 0; c < NCH; ++c) {
        CP_WAIT(1);          // chunk c complete
        __syncthreads();     // everyone done reading stage (c-1) == stage ldst

        if (c + 2 < NCH) {   // prefetch chunk c+2 into the just-freed stage
            issue_loads<KK>(aptr, bptr, sbase + (uint32_t)ldst * STAGE_BYTES + dA,
                            sbase + (uint32_t)ldst * STAGE_BYTES + dB);
            aptr += 64; bptr += 64;
            ldst = (ldst + 1 == NSTAGE) ? 0 : ldst + 1;
        }
        CP_COMMIT();

        const uint32_t sa = sbase + (uint32_t)cst * STAGE_BYTES;
        cst = (cst + 1 == NSTAGE) ? 0 : cst + 1;
#pragma unroll
        for (int kk = 0; kk < 4; ++kk) {
            const uint32_t kx = (uint32_t)(kk << 5);
            uint32_t afr[4][4];
#pragma unroll
            for (int mt = 0; mt < 4; ++mt)
                ldsm_x4(afr[mt], sa + (aoff[mt] ^ kx));
            uint32_t bfr[2][4];
#pragma unroll
            for (int np = 0; np < 2; ++np)
                ldsm_x4(bfr[np], sa + (boff[np] ^ kx));
#pragma unroll
            for (int mt = 0; mt < 4; ++mt)
#pragma unroll
                for (int nt = 0; nt < 4; ++nt)
                    mma16816(acc[mt][nt], afr[mt], bfr[nt >> 1][nt & 1], bfr[nt >> 1][(nt & 1) + 2]);
        }
    }

    // ---------------- epilogue: direct float2 stores (32B-sector aligned) ----------------
    const int qr = lane >> 2;          // 0..7
    const int qc = (lane & 3) * 2;     // 0,2,4,6

    int act;     // uniform per CTA
    const float* bp;
    int bbase;
    if (MODE == 0) {
        const int gate = m0 >> 11;     // 128-row tile lies in one gate
        act = (gate < 3) ? 0 : 1;
        bp = (gate == 0) ? bias0 : (gate == 1) ? bias1 : (gate == 2) ? bias2 : bias3;
        bbase = m0 & (NH - 1);
    } else {
        act = 2;
        bp = bias0;
        bbase = m0;
    }

#pragma unroll
    for (int mt = 0; mt < 4; ++mt) {
        const int r1 = m0 + warpm * 64 + mt * 16 + qr;
        const float bv0 = bp[bbase + warpm * 64 + mt * 16 + qr];
        const float bv1 = bp[bbase + warpm * 64 + mt * 16 + qr + 8];
#pragma unroll
        for (int nt = 0; nt < 4; ++nt) {
            const int col = n0 + warpn * 32 + nt * 8 + qc;
            float2 v0, v1;
            v0.x = apply_act(acc[mt][nt][0] + bv0, act);
            v0.y = apply_act(acc[mt][nt][1] + bv0, act);
            v1.x = apply_act(acc[mt][nt][2] + bv1, act);
            v1.y = apply_act(acc[mt][nt][3] + bv1, act);
            *(float2*)(outp + (size_t)r1 * BATCH + col) = v0;
            *(float2*)(outp + (size_t)(r1 + 8) * BATCH + col) = v1;
        }
    }
}

// ---------------- fused prep: convert_Wg + transpose_h + emb_gather in ONE launch ----------
#define PREP_CONV_CTAS 4096
#define PREP_TR_CTAS   4096   // (2048/32) x (2048/32)
#define PREP_EMB_CTAS  2048

__global__ void __launch_bounds__(256)
prep_fused(const float4* __restrict__ wf, const float4* __restrict__ wi,
           const float4* __restrict__ wo, const float4* __restrict__ wc,
           const float* __restrict__ h_prev,
           const int* __restrict__ idx, const float* __restrict__ emb) {
    __shared__ float tile[32][33];
    const int bid = blockIdx.x;
    const int tid = threadIdx.x;

    if (bid < PREP_CONV_CTAS) {
        const size_t N4 = (size_t)NH * KG / 4;
        size_t i = (size_t)bid * 256 + tid;
        const size_t stride = (size_t)PREP_CONV_CTAS * 256;
        for (; i < 4 * N4; i += stride) {
            const int g = (int)(i / N4);
            const size_t j = i - (size_t)g * N4;
            const float4* s = (g == 0) ? wf : (g == 1) ? wi : (g == 2) ? wo : wc;
            float4 v = s[j];
            __half2* d = (__half2*)(g_Wg + (size_t)g * NH * KG + j * 4);
            d[0] = __floats2half2_rn(v.x, v.y);
            d[1] = __floats2half2_rn(v.z, v.w);
        }
    } else if (bid < PREP_CONV_CTAS + PREP_TR_CTAS) {
        // transpose h_prev [2048(n)][2048(b)] -> g_zT[b][n] fp16
        const int b2 = bid - PREP_CONV_CTAS;
        const int b0 = (b2 & 63) * 32;
        const int n0 = (b2 >> 6) * 32;
        const int tx = tid & 31, ty = tid >> 5;   // 32 x 8
#pragma unroll
        for (int j = 0; j < 4; ++j)
            tile[ty + 8 * j][tx] = h_prev[(size_t)(n0 + ty + 8 * j) * BATCH + b0 + tx];
        __syncthreads();
#pragma unroll
        for (int j = 0; j < 4; ++j)
            g_zT[(size_t)(b0 + ty + 8 * j) * KG + n0 + tx] = __float2half(tile[tx][ty + 8 * j]);
    } else {
        const int b = bid - PREP_CONV_CTAS - PREP_TR_CTAS;
        const int r = idx[b];
        const float4* s = (const float4*)(emb + (size_t)r * DIMV);
        __half2* d = (__half2*)(g_zT + (size_t)b * KG + NH);
        float4 v = s[tid];                      // 256 threads, 256 float4
        d[tid * 2 + 0] = __floats2half2_rn(v.x, v.y);
        d[tid * 2 + 1] = __floats2half2_rn(v.z, v.w);
    }
}

// C = f*C_prev + i*tC; h = o*tanh(C); write outC/outH f32 + g_hT fp16 (transposed)
__global__ void cell_update(const float* __restrict__ Cprev,
                            float* __restrict__ outC, float* __restrict__ outH) {
    __shared__ float tile[32][33];
    const int n0 = blockIdx.y * 32, b0 = blockIdx.x * 32;
    const int tx = threadIdx.x, ty = threadIdx.y;
    const size_t GS = (size_t)NH * BATCH;
#pragma unroll
    for (int j = 0; j < 4; ++j) {
        const int n = n0 + ty + 8 * j;
        const size_t off = (size_t)n * BATCH + b0 + tx;
        const float f  = g_gates[off];
        const float ii = g_gates[GS + off];
        const float o  = g_gates[2 * GS + off];
        const float tc = g_gates[3 * GS + off];
        const float c = f * Cprev[off] + ii * tc;
        const float h = o * tanhf(c);
        outC[off] = c;
        outH[off] = h;
        tile[ty + 8 * j][tx] = h;
    }
    __syncthreads();
#pragma unroll
    for (int j = 0; j < 4; ++j)
        g_hT[(size_t)(b0 + ty + 8 * j) * KA + n0 + tx] = __float2half(tile[tx][ty + 8 * j]);
}

// ---------------- launch ----------------
extern "C" void kernel_launch(void* const* d_in, const int* in_sizes, int n_in,
                              void* d_out, int out_size) {
    const int*   itext  = (const int*)d_in[0];
    const float* h_prev = (const float*)d_in[1];
    const float* C_prev = (const float*)d_in[2];
    const float* emb    = (const float*)d_in[3];
    const float* W_A    = (const float*)d_in[4];
    const float* W_C    = (const float*)d_in[5];
    const float* W_f    = (const float*)d_in[6];
    const float* W_o    = (const float*)d_in[7];
    const float* W_i    = (const float*)d_in[8];
    const float* b_A    = (const float*)d_in[9];
    const float* b_C    = (const float*)d_in[10];
    const float* b_f    = (const float*)d_in[11];
    const float* b_o    = (const float*)d_in[12];
    const float* b_i    = (const float*)d_in[13];

    float* outY = (float*)d_out;                       // [32000][2048]
    float* outH = outY + (size_t)MV * BATCH;           // [2048][2048]
    float* outC = outH + (size_t)NH * BATCH;           // [2048][2048]

    cudaFuncSetAttribute(gemm_f16<0>, cudaFuncAttributeMaxDynamicSharedMemorySize, GEMM_SMEM);
    cudaFuncSetAttribute(gemm_f16<1>, cudaFuncAttributeMaxDynamicSharedMemorySize, GEMM_SMEM);

    // fused prep (all inputs of gemm0 in one launch; parts overlap each other)
    prep_fused<<<PREP_CONV_CTAS + PREP_TR_CTAS + PREP_EMB_CTAS, 256>>>(
        (const float4*)W_f, (const float4*)W_i, (const float4*)W_o, (const float4*)W_C,
        h_prev, itext, emb);

    // gate GEMMs (stacked M=8192, N=2048) + fused W_A conversion in trailing CTAs
    gemm_f16<0><<<GEMM0_CTAS + CONV_CTAS, 256, GEMM_SMEM>>>(b_f, b_i, b_o, b_C, nullptr,
                                                            (const float4*)W_A);

    // cell update + h transpose
    {
        dim3 g(BATCH / 32, NH / 32), b(32, 8);
        cell_update<<<g, b>>>(C_prev, outC, outH);
    }

    // vocab projection
    gemm_f16<1><<<(MV / 128) * (BATCH / 128), 256, GEMM_SMEM>>>(b_A, nullptr, nullptr, nullptr,
                                                                outY, nullptr);

    (void)in_sizes; (void)n_in; (void)out_size;
}

// round 15
// speedup vs baseline: 1.0895x; 1.0204x over previous
#include <cuda_runtime.h>
#include <cuda_fp16.h>
#include <cstdint>

#define DI __device__ __forceinline__

// ---------------- problem sizes ----------------
#define MV    32000   // vocab
#define NH    2048    // hidden
#define DIMV  1024    // embed dim
#define BATCH 2048    // batch
#define KG    (NH + DIMV)   // 3072 (gate GEMM K)
#define KA    NH            // 2048 (W_A GEMM K)

// ---------------- device scratch (allocation-free rule) ----------------
__device__ __align__(128) __half g_Wg[(size_t)4 * NH * KG];       // fp16 gate weights, stacked f,i,o,C
__device__ __align__(128) __half g_WA[(size_t)MV * KA];           // fp16 W_A
__device__ __align__(128) __half g_zT[(size_t)BATCH * KG];        // z^T  [B][3072] K-major
__device__ __align__(128) __half g_hT[(size_t)BATCH * KA];        // h^T  [B][2048] K-major
__device__ __align__(128) float  g_gates[(size_t)4 * NH * BATCH]; // activated f,i,o,tanh(WCz+b)

// ---------------- PTX helpers (sm_80-era: valid on plain sm_103 target) ----------------
DI uint32_t smem_u32(const void* p) {
    uint32_t a;
    asm("{ .reg .u64 t; cvta.to.shared.u64 t, %1; cvt.u32.u64 %0, t; }" : "=r"(a) : "l"(p));
    return a;
}

DI void ldsm_x4(uint32_t* r, uint32_t addr) {
    asm volatile("ldmatrix.sync.aligned.m8n8.x4.shared.b16 {%0,%1,%2,%3}, [%4];"
                 : "=r"(r[0]), "=r"(r[1]), "=r"(r[2]), "=r"(r[3]) : "r"(addr));
}

DI void mma16816(float* c, const uint32_t* a, uint32_t b0, uint32_t b1) {
    asm volatile("mma.sync.aligned.m16n8k16.row.col.f32.f16.f16.f32 "
                 "{%0,%1,%2,%3}, {%4,%5,%6,%7}, {%8,%9}, {%0,%1,%2,%3};"
                 : "+f"(c[0]), "+f"(c[1]), "+f"(c[2]), "+f"(c[3])
                 : "r"(a[0]), "r"(a[1]), "r"(a[2]), "r"(a[3]), "r"(b0), "r"(b1));
}

#define CP_ASYNC16(dst, src) \
    asm volatile("cp.async.cg.shared.global [%0], [%1], 16;" :: "r"(dst), "l"(src) : "memory")
#define CP_COMMIT() asm volatile("cp.async.commit_group;" ::: "memory")
#define CP_WAIT(n)  asm volatile("cp.async.wait_group %0;" :: "n"(n) : "memory")

// ---------------- GEMM: D[m][n] = sum_k A[m][k]*B[n][k], A,B fp16 K-major ----------------
// BM=BN=128, BK=64 (128B rows, XOR-16B swizzle). 3-stage cp.async pipeline, 96KB smem
// -> 2 CTAs/SM (16 warps/SM). 256 threads = 8 warps as 2(m) x 4(n): warp tile 64x32.
// B fragments double-buffered across kk (A single-buffered: reg budget is exactly 128).
#define NSTAGE 3
#define STAGE_BYTES 32768            // A tile 16KB + B tile 16KB
#define GEMM_SMEM (NSTAGE * STAGE_BYTES)  // 98304

// 8 cp.async per thread (256 threads): A tile rows (tid>>3)+32j, B same
template <int KK>
DI void issue_loads(const __half* a, const __half* b, uint32_t dstA, uint32_t dstB) {
#pragma unroll
    for (int it = 0; it < 4; ++it)
        CP_ASYNC16(dstA + (uint32_t)(it * 4096), a + (size_t)it * 32 * KK);
#pragma unroll
    for (int it = 0; it < 4; ++it)
        CP_ASYNC16(dstB + (uint32_t)(it * 4096), b + (size_t)it * 32 * KK);
}

DI float apply_act(float v, int act) {  // 0: sigmoid, 1: tanh, 2: none
    if (act == 0) return 1.0f / (1.0f + __expf(-v));
    if (act == 1) return tanhf(v);
    return v;
}

#define GEMM0_CTAS 1024   // (8192/128) * (2048/128)
#define CONV_CTAS  1024   // trailing CTAs of gemm0 grid: convert W_A under the GEMM

// MODE 0: gates GEMM (A=g_Wg stacked [8192][3072], B=g_zT, sigmoid/tanh epilogue -> g_gates)
//         + trailing CTAs convert W_A f32 -> g_WA fp16 (DRAM idle under GEMM)
// MODE 1: W_A GEMM  (A=g_WA [32000][2048], B=g_hT, bias epilogue -> y)
template <int MODE>
__global__ void __launch_bounds__(256, 2)
gemm_f16(const float* __restrict__ bias0, const float* __restrict__ bias1,
         const float* __restrict__ bias2, const float* __restrict__ bias3,
         float* __restrict__ outy, const float4* __restrict__ convsrc) {
    constexpr int KK  = (MODE == 0) ? KG : KA;
    constexpr int NCH = KK / 64;

    if (MODE == 0 && blockIdx.x >= GEMM0_CTAS) {
        // ---- fused W_A conversion (grid-stride) ----
        const size_t N4 = (size_t)MV * KA / 4;
        size_t i = (size_t)(blockIdx.x - GEMM0_CTAS) * 256 + threadIdx.x;
        const size_t stride = (size_t)CONV_CTAS * 256;
        for (; i < N4; i += stride) {
            float4 v = convsrc[i];
            __half2* d = (__half2*)(g_WA + i * 4);
            d[0] = __floats2half2_rn(v.x, v.y);
            d[1] = __floats2half2_rn(v.z, v.w);
        }
        return;
    }

    const __half* A = (MODE == 0) ? g_Wg : g_WA;
    const __half* B = (MODE == 0) ? g_zT : g_hT;
    float* outp = (MODE == 0) ? g_gates : outy;

    extern __shared__ __align__(1024) char smem[];
    const uint32_t sbase = smem_u32(smem);
    const int tid = threadIdx.x;
    const int lane = tid & 31;
    const int warp = tid >> 5;
    const int warpm = warp & 1;       // 2 warps over m: warp tile 64
    const int warpn = warp >> 1;      // 4 warps over n: warp tile 32

    // n fastest -> 16 consecutive CTAs share one A tile (L2 reuse of big operand)
    const int n0 = (blockIdx.x & 15) * 128;
    const int m0 = (blockIdx.x >> 4) * 128;

    float acc[4][4][4];
#pragma unroll
    for (int i = 0; i < 4; ++i)
#pragma unroll
        for (int j = 0; j < 4; ++j)
#pragma unroll
            for (int k = 0; k < 4; ++k) acc[i][j][k] = 0.0f;

    const int lrow = lane & 15;
    const int lhi  = lane >> 4;

    // hoisted ldsm offsets (relative to stage base); per-kstep addr = base ^ (kk<<5)
    uint32_t aoff[4], boff[2];
#pragma unroll
    for (int mt = 0; mt < 4; ++mt) {
        const int row = warpm * 64 + mt * 16 + lrow;
        aoff[mt] = (uint32_t)row * 128u + (uint32_t)((lhi ^ (row & 7)) << 4);
    }
#pragma unroll
    for (int np = 0; np < 2; ++np) {
        const int nrow = warpn * 32 + np * 16 + lrow;
        boff[np] = 16384u + (uint32_t)nrow * 128u + (uint32_t)((lhi ^ (nrow & 7)) << 4);
    }

    // loader per-thread state (strength-reduced): base pointers + fixed smem offsets
    const int ltr = tid >> 3;         // base row 0..31
    const int ltc = tid & 7;          // 16B-group column
    const uint32_t dA = (uint32_t)ltr * 128u + (uint32_t)((ltc ^ (ltr & 7)) << 4);
    const uint32_t dB = 16384u + dA;  // same formula for the B half of the stage
    const __half* aptr = A + (size_t)(m0 + ltr) * KK + ltc * 8;
    const __half* bptr = B + (size_t)(n0 + ltr) * KK + ltc * 8;

    // prologue: 2 chunks in flight
    issue_loads<KK>(aptr, bptr, sbase + dA, sbase + dB);
    CP_COMMIT();
    issue_loads<KK>(aptr + 64, bptr + 64, sbase + STAGE_BYTES + dA, sbase + STAGE_BYTES + dB);
    CP_COMMIT();
    aptr += 128; bptr += 128;

    int ldst = 2;   // stage receiving the next load
    int cst  = 0;   // stage being computed
    for (int c = 0; c < NCH; ++c) {
        CP_WAIT(1);          // chunk c complete
        __syncthreads();     // everyone done reading stage (c-1) == stage ldst

        if (c + 2 < NCH) {   // prefetch chunk c+2 into the just-freed stage
            issue_loads<KK>(aptr, bptr, sbase + (uint32_t)ldst * STAGE_BYTES + dA,
                            sbase + (uint32_t)ldst * STAGE_BYTES + dB);
            aptr += 64; bptr += 64;
            ldst = (ldst + 1 == NSTAGE) ? 0 : ldst + 1;
        }
        CP_COMMIT();

        const uint32_t sa = sbase + (uint32_t)cst * STAGE_BYTES;
        cst = (cst + 1 == NSTAGE) ? 0 : cst + 1;

        // B fragments double-buffered across kk; A single-buffered
        uint32_t bfr[2][2][4];
#pragma unroll
        for (int np = 0; np < 2; ++np)
            ldsm_x4(bfr[0][np], sa + boff[np]);

#pragma unroll
        for (int kk = 0; kk < 4; ++kk) {
            const int cur = kk & 1, nxt = cur ^ 1;
            const uint32_t kx = (uint32_t)(kk << 5);
            uint32_t afr[4][4];
#pragma unroll
            for (int mt = 0; mt < 4; ++mt)
                ldsm_x4(afr[mt], sa + (aoff[mt] ^ kx));
            if (kk < 3) {    // prefetch next kk's B before consuming this kk
                const uint32_t kx2 = (uint32_t)((kk + 1) << 5);
#pragma unroll
                for (int np = 0; np < 2; ++np)
                    ldsm_x4(bfr[nxt][np], sa + (boff[np] ^ kx2));
            }
#pragma unroll
            for (int mt = 0; mt < 4; ++mt)
#pragma unroll
                for (int nt = 0; nt < 4; ++nt)
                    mma16816(acc[mt][nt], afr[mt],
                             bfr[cur][nt >> 1][nt & 1], bfr[cur][nt >> 1][(nt & 1) + 2]);
        }
    }

    // ---------------- epilogue: direct float2 stores (32B-sector aligned) ----------------
    const int qr = lane >> 2;          // 0..7
    const int qc = (lane & 3) * 2;     // 0,2,4,6

    int act;     // uniform per CTA
    const float* bp;
    int bbase;
    if (MODE == 0) {
        const int gate = m0 >> 11;     // 128-row tile lies in one gate
        act = (gate < 3) ? 0 : 1;
        bp = (gate == 0) ? bias0 : (gate == 1) ? bias1 : (gate == 2) ? bias2 : bias3;
        bbase = m0 & (NH - 1);
    } else {
        act = 2;
        bp = bias0;
        bbase = m0;
    }

#pragma unroll
    for (int mt = 0; mt < 4; ++mt) {
        const int r1 = m0 + warpm * 64 + mt * 16 + qr;
        const float bv0 = bp[bbase + warpm * 64 + mt * 16 + qr];
        const float bv1 = bp[bbase + warpm * 64 + mt * 16 + qr + 8];
#pragma unroll
        for (int nt = 0; nt < 4; ++nt) {
            const int col = n0 + warpn * 32 + nt * 8 + qc;
            float2 v0, v1;
            v0.x = apply_act(acc[mt][nt][0] + bv0, act);
            v0.y = apply_act(acc[mt][nt][1] + bv0, act);
            v1.x = apply_act(acc[mt][nt][2] + bv1, act);
            v1.y = apply_act(acc[mt][nt][3] + bv1, act);
            *(float2*)(outp + (size_t)r1 * BATCH + col) = v0;
            *(float2*)(outp + (size_t)(r1 + 8) * BATCH + col) = v1;
        }
    }
}

// ---------------- fused prep: convert_Wg + transpose_h + emb_gather in ONE launch ----------
#define PREP_CONV_CTAS 4096
#define PREP_TR_CTAS   4096   // (2048/32) x (2048/32)
#define PREP_EMB_CTAS  2048

__global__ void __launch_bounds__(256)
prep_fused(const float4* __restrict__ wf, const float4* __restrict__ wi,
           const float4* __restrict__ wo, const float4* __restrict__ wc,
           const float* __restrict__ h_prev,
           const int* __restrict__ idx, const float* __restrict__ emb) {
    __shared__ float tile[32][33];
    const int bid = blockIdx.x;
    const int tid = threadIdx.x;

    if (bid < PREP_CONV_CTAS) {
        const size_t N4 = (size_t)NH * KG / 4;
        size_t i = (size_t)bid * 256 + tid;
        const size_t stride = (size_t)PREP_CONV_CTAS * 256;
        for (; i < 4 * N4; i += stride) {
            const int g = (int)(i / N4);
            const size_t j = i - (size_t)g * N4;
            const float4* s = (g == 0) ? wf : (g == 1) ? wi : (g == 2) ? wo : wc;
            float4 v = s[j];
            __half2* d = (__half2*)(g_Wg + (size_t)g * NH * KG + j * 4);
            d[0] = __floats2half2_rn(v.x, v.y);
            d[1] = __floats2half2_rn(v.z, v.w);
        }
    } else if (bid < PREP_CONV_CTAS + PREP_TR_CTAS) {
        // transpose h_prev [2048(n)][2048(b)] -> g_zT[b][n] fp16
        const int b2 = bid - PREP_CONV_CTAS;
        const int b0 = (b2 & 63) * 32;
        const int n0 = (b2 >> 6) * 32;
        const int tx = tid & 31, ty = tid >> 5;   // 32 x 8
#pragma unroll
        for (int j = 0; j < 4; ++j)
            tile[ty + 8 * j][tx] = h_prev[(size_t)(n0 + ty + 8 * j) * BATCH + b0 + tx];
        __syncthreads();
#pragma unroll
        for (int j = 0; j < 4; ++j)
            g_zT[(size_t)(b0 + ty + 8 * j) * KG + n0 + tx] = __float2half(tile[tx][ty + 8 * j]);
    } else {
        const int b = bid - PREP_CONV_CTAS - PREP_TR_CTAS;
        const int r = idx[b];
        const float4* s = (const float4*)(emb + (size_t)r * DIMV);
        __half2* d = (__half2*)(g_zT + (size_t)b * KG + NH);
        float4 v = s[tid];                      // 256 threads, 256 float4
        d[tid * 2 + 0] = __floats2half2_rn(v.x, v.y);
        d[tid * 2 + 1] = __floats2half2_rn(v.z, v.w);
    }
}

// C = f*C_prev + i*tC; h = o*tanh(C); write outC/outH f32 + g_hT fp16 (transposed)
__global__ void cell_update(const float* __restrict__ Cprev,
                            float* __restrict__ outC, float* __restrict__ outH) {
    __shared__ float tile[32][33];
    const int n0 = blockIdx.y * 32, b0 = blockIdx.x * 32;
    const int tx = threadIdx.x, ty = threadIdx.y;
    const size_t GS = (size_t)NH * BATCH;
#pragma unroll
    for (int j = 0; j < 4; ++j) {
        const int n = n0 + ty + 8 * j;
        const size_t off = (size_t)n * BATCH + b0 + tx;
        const float f  = g_gates[off];
        const float ii = g_gates[GS + off];
        const float o  = g_gates[2 * GS + off];
        const float tc = g_gates[3 * GS + off];
        const float c = f * Cprev[off] + ii * tc;
        const float h = o * tanhf(c);
        outC[off] = c;
        outH[off] = h;
        tile[ty + 8 * j][tx] = h;
    }
    __syncthreads();
#pragma unroll
    for (int j = 0; j < 4; ++j)
        g_hT[(size_t)(b0 + ty + 8 * j) * KA + n0 + tx] = __float2half(tile[tx][ty + 8 * j]);
}

// ---------------- launch ----------------
extern "C" void kernel_launch(void* const* d_in, const int* in_sizes, int n_in,
                              void* d_out, int out_size) {
    const int*   itext  = (const int*)d_in[0];
    const float* h_prev = (const float*)d_in[1];
    const float* C_prev = (const float*)d_in[2];
    const float* emb    = (const float*)d_in[3];
    const float* W_A    = (const float*)d_in[4];
    const float* W_C    = (const float*)d_in[5];
    const float* W_f    = (const float*)d_in[6];
    const float* W_o    = (const float*)d_in[7];
    const float* W_i    = (const float*)d_in[8];
    const float* b_A    = (const float*)d_in[9];
    const float* b_C    = (const float*)d_in[10];
    const float* b_f    = (const float*)d_in[11];
    const float* b_o    = (const float*)d_in[12];
    const float* b_i    = (const float*)d_in[13];

    float* outY = (float*)d_out;                       // [32000][2048]
    float* outH = outY + (size_t)MV * BATCH;           // [2048][2048]
    float* outC = outH + (size_t)NH * BATCH;           // [2048][2048]

    cudaFuncSetAttribute(gemm_f16<0>, cudaFuncAttributeMaxDynamicSharedMemorySize, GEMM_SMEM);
    cudaFuncSetAttribute(gemm_f16<1>, cudaFuncAttributeMaxDynamicSharedMemorySize, GEMM_SMEM);

    // fused prep (all inputs of gemm0 in one launch; parts overlap each other)
    prep_fused<<<PREP_CONV_CTAS + PREP_TR_CTAS + PREP_EMB_CTAS, 256>>>(
        (const float4*)W_f, (const float4*)W_i, (const float4*)W_o, (const float4*)W_C,
        h_prev, itext, emb);

    // gate GEMMs (stacked M=8192, N=2048) + fused W_A conversion in trailing CTAs
    gemm_f16<0><<<GEMM0_CTAS + CONV_CTAS, 256, GEMM_SMEM>>>(b_f, b_i, b_o, b_C, nullptr,
                                                            (const float4*)W_A);

    // cell update + h transpose
    {
        dim3 g(BATCH / 32, NH / 32), b(32, 8);
        cell_update<<<g, b>>>(C_prev, outC, outH);
    }

    // vocab projection
    gemm_f16<1><<<(MV / 128) * (BATCH / 128), 256, GEMM_SMEM>>>(b_A, nullptr, nullptr, nullptr,
                                                                outY, nullptr);

    (void)in_sizes; (void)n_in; (void)out_size;
}